// round 8
// baseline (speedup 1.0000x reference)
#include <cuda_runtime.h>
#include <math.h>

// SPH step — slot counting sort + preloaded-row predicated gather-reduce.
// inputs: r [N,3] f32, v [N,3] f32, i_s [E] i32 (receivers), j_s [E] i32 (senders)
// output: [N,8] f32 = [rho, p, dudt.xyz, 0,0,0]

#define SIGMA_F 0.0026599711f            /* 3/(359*pi), H=1 */
#define P_REF_F 100.0f
#define EPS_F   1e-8f
#define ETA_IJ_F (2.0f * 0.01f * 0.01f / (0.01f + 0.01f + 1e-8f))

#define MAXN_P 131072          // >= N (N = 100,000)
#define SLOT_SHIFT 7           // 128 slots per particle (Poisson(32) max ~75)
#define SLOT (1 << SLOT_SHIFT)

struct __align__(32) Pk { float4 a; float4 b; };  // a={x,y,z,rho} b={vx,vy,vz,0}

__device__ int g_counts[MAXN_P];
__device__ int g_slots[MAXN_P << SLOT_SHIFT];     // 64 MB, rows always fully allocated
__device__ Pk  g_pack[MAXN_P];

__device__ __forceinline__ float quintic_w(float d) {
    float a = fmaxf(0.0f, 1.0f - d);
    float b = fmaxf(0.0f, 2.0f - d);
    float c = fmaxf(0.0f, 3.0f - d);
    float a5 = a * a; a5 = a5 * a5 * a;
    float b5 = b * b; b5 = b5 * b5 * b;
    float c5 = c * c; c5 = c5 * c5 * c;
    return SIGMA_F * (c5 - 6.0f * b5 + 15.0f * a5);
}

__device__ __forceinline__ float quintic_grad_w(float d) {
    float a = fmaxf(0.0f, 1.0f - d);
    float b = fmaxf(0.0f, 2.0f - d);
    float c = fmaxf(0.0f, 3.0f - d);
    float a4 = a * a; a4 = a4 * a4;
    float b4 = b * b; b4 = b4 * b4;
    float c4 = c * c; c4 = c4 * c4;
    return SIGMA_F * (-5.0f * c4 + 30.0f * b4 - 75.0f * a4);
}

// --------------------------------------------------------------------------
__global__ void pack_zero_kernel(const float* __restrict__ r,
                                 const float* __restrict__ v, int N) {
    int i = blockIdx.x * blockDim.x + threadIdx.x;
    if (i >= N) return;
    float4 a = make_float4(__ldg(&r[3*i]), __ldg(&r[3*i+1]), __ldg(&r[3*i+2]), 0.0f);
    float4 b = make_float4(__ldg(&v[3*i]), __ldg(&v[3*i+1]), __ldg(&v[3*i+2]), 0.0f);
    g_pack[i].a = a;
    g_pack[i].b = b;
    g_counts[i] = 0;
}

// --------------------------------------------------------------------------
// slot-based counting scatter; 4 edges per thread via int4 loads (R4 version)
__global__ void scatter_kernel(const int* __restrict__ i_s,
                               const int* __restrict__ j_s, int E) {
    int t = blockIdx.x * blockDim.x + threadIdx.x;
    int base = t * 4;
    if (base + 3 < E) {
        int4 ii = *(const int4*)(i_s + base);
        int4 jj = *(const int4*)(j_s + base);
        int p;
        p = atomicAdd(&g_counts[ii.x], 1); if (p < SLOT) g_slots[(ii.x << SLOT_SHIFT) + p] = jj.x;
        p = atomicAdd(&g_counts[ii.y], 1); if (p < SLOT) g_slots[(ii.y << SLOT_SHIFT) + p] = jj.y;
        p = atomicAdd(&g_counts[ii.z], 1); if (p < SLOT) g_slots[(ii.z << SLOT_SHIFT) + p] = jj.z;
        p = atomicAdd(&g_counts[ii.w], 1); if (p < SLOT) g_slots[(ii.w << SLOT_SHIFT) + p] = jj.w;
    } else {
        for (int e = base; e < E; e++) {
            int i = i_s[e];
            int p = atomicAdd(&g_counts[i], 1);
            if (p < SLOT) g_slots[(i << SLOT_SHIFT) + p] = j_s[e];
        }
    }
}

// --------------------------------------------------------------------------
// 16 lanes per particle; preloaded int4 of slot indices (64 slots/iter),
// predicated gathers — no wasted memory traffic, single row load for
// deg <= 64 (99.8% of particles).
__global__ void rho_gather_kernel(int N) {
    int tid = blockIdx.x * blockDim.x + threadIdx.x;
    int i = tid >> 4;
    int sl = threadIdx.x & 15;
    if (i >= N) return;
    int deg = g_counts[i];
    if (deg > SLOT) deg = SLOT;
    const int4* row4 = (const int4*)&g_slots[i << SLOT_SHIFT];
    float4 Pi = g_pack[i].a;
    float sum = 0.0f;
    for (int t = 0; t * 64 < deg; t++) {
        int4 jj = row4[t * 16 + sl];          // always in-bounds (row = 128 ints)
        int s0 = t * 64 + 4 * sl;
        #pragma unroll
        for (int u = 0; u < 4; u++) {
            int j = (u == 0) ? jj.x : (u == 1) ? jj.y : (u == 2) ? jj.z : jj.w;
            if (s0 + u < deg) {
                float4 Pj = g_pack[j].a;
                float dx = Pi.x - Pj.x, dy = Pi.y - Pj.y, dz = Pi.z - Pj.z;
                sum += quintic_w(sqrtf(dx*dx + dy*dy + dz*dz));
            }
        }
    }
    #pragma unroll
    for (int o = 8; o; o >>= 1) sum += __shfl_xor_sync(~0u, sum, o);
    if (sl == 0) g_pack[i].a.w = sum;
}

// --------------------------------------------------------------------------
// 16 lanes per particle; writes all 8 output columns via two float4 stores.
__global__ void force_gather_kernel(float* __restrict__ out, int N) {
    int tid = blockIdx.x * blockDim.x + threadIdx.x;
    int i = tid >> 4;
    int sl = threadIdx.x & 15;
    if (i >= N) return;
    int deg = g_counts[i];
    if (deg > SLOT) deg = SLOT;
    const int4* row4 = (const int4*)&g_slots[i << SLOT_SHIFT];
    float4 Pa_i = g_pack[i].a;
    float4 Pb_i = g_pack[i].b;
    float rho_i = Pa_i.w;
    float inv_i = __fdividef(1.0f, rho_i);
    float inv_i2 = inv_i * inv_i;

    float ax = 0.0f, ay = 0.0f, az = 0.0f;
    for (int t = 0; t * 64 < deg; t++) {
        int4 jj = row4[t * 16 + sl];
        int s0 = t * 64 + 4 * sl;
        #pragma unroll
        for (int u = 0; u < 4; u++) {
            int j = (u == 0) ? jj.x : (u == 1) ? jj.y : (u == 2) ? jj.z : jj.w;
            if (s0 + u < deg) {
                float4 Pa_j = g_pack[j].a;
                float4 Pb_j = g_pack[j].b;
                float dx = Pa_i.x - Pa_j.x, dy = Pa_i.y - Pa_j.y, dz = Pa_i.z - Pa_j.z;
                float d = sqrtf(dx*dx + dy*dy + dz*dz);
                float rho_j = Pa_j.w;
                // p_ij = (rho_j*p_i + rho_i*p_j)/(rho_i+rho_j) = 100*(2 rho_i rho_j/s - 1)
                float inv_s = __fdividef(1.0f, rho_i + rho_j);
                float p_ij = P_REF_F * (2.0f * rho_i * rho_j * inv_s - 1.0f);
                float inv_j = __fdividef(1.0f, rho_j);
                float wvol = inv_i2 + inv_j * inv_j;
                float c = wvol * quintic_grad_w(d) * __fdividef(1.0f, d + EPS_F);
                float dvx = Pb_i.x - Pb_j.x, dvy = Pb_i.y - Pb_j.y, dvz = Pb_i.z - Pb_j.z;
                ax += c * (-p_ij * dx + ETA_IJ_F * dvx);
                ay += c * (-p_ij * dy + ETA_IJ_F * dvy);
                az += c * (-p_ij * dz + ETA_IJ_F * dvz);
            }
        }
    }
    #pragma unroll
    for (int o = 8; o; o >>= 1) {
        ax += __shfl_xor_sync(~0u, ax, o);
        ay += __shfl_xor_sync(~0u, ay, o);
        az += __shfl_xor_sync(~0u, az, o);
    }
    if (sl == 0) {
        float4* o4 = (float4*)(out + 8 * i);
        o4[0] = make_float4(rho_i, P_REF_F * (rho_i - 1.0f), ax, ay);
        o4[1] = make_float4(az, 0.0f, 0.0f, 0.0f);
    }
}

// --------------------------------------------------------------------------
extern "C" void kernel_launch(void* const* d_in, const int* in_sizes, int n_in,
                              void* d_out, int out_size) {
    const float* r   = (const float*)d_in[0];
    const float* v   = (const float*)d_in[1];
    const int*   i_s = (const int*)d_in[2];
    const int*   j_s = (const int*)d_in[3];
    float* out = (float*)d_out;

    int N = in_sizes[0] / 3;
    int E = in_sizes[2];

    const int TB = 256;
    pack_zero_kernel<<<(N + TB - 1) / TB, TB>>>(r, v, N);
    int nthreads = (E + 3) / 4;
    scatter_kernel<<<(nthreads + TB - 1) / TB, TB>>>(i_s, j_s, E);
    // 16 lanes per particle -> 16 particles per 256-thread block
    int gblocks = (N + 15) / 16;
    rho_gather_kernel<<<gblocks, TB>>>(N);
    force_gather_kernel<<<gblocks, TB>>>(out, N);
}

// round 9
// speedup vs baseline: 1.0477x; 1.0477x over previous
#include <cuda_runtime.h>
#include <math.h>

// SPH step — slot counting sort + predicated gather-reduce.
// inputs: r [N,3] f32, v [N,3] f32, i_s [E] i32 (receivers), j_s [E] i32 (senders)
// output: [N,8] f32 = [rho, p, dudt.xyz, 0,0,0]
//
// rho:   8 lanes/particle  x int4 row load  (32 slots/iter, matched to mean deg)
// force: 16 lanes/particle x int4 row load  (64 slots/iter, heavy math hides idle lanes)

#define SIGMA_F 0.0026599711f            /* 3/(359*pi), H=1 */
#define P_REF_F 100.0f
#define EPS_F   1e-8f
#define ETA_IJ_F (2.0f * 0.01f * 0.01f / (0.01f + 0.01f + 1e-8f))

#define MAXN_P 131072          // >= N (N = 100,000)
#define SLOT_SHIFT 7           // 128 slots per particle (Poisson(32) max ~75)
#define SLOT (1 << SLOT_SHIFT)

struct __align__(32) Pk { float4 a; float4 b; };  // a={x,y,z,rho} b={vx,vy,vz,0}

__device__ int g_counts[MAXN_P];
__device__ int g_slots[MAXN_P << SLOT_SHIFT];     // 64 MB, rows always fully allocated
__device__ Pk  g_pack[MAXN_P];

__device__ __forceinline__ float quintic_w(float d) {
    float a = fmaxf(0.0f, 1.0f - d);
    float b = fmaxf(0.0f, 2.0f - d);
    float c = fmaxf(0.0f, 3.0f - d);
    float a5 = a * a; a5 = a5 * a5 * a;
    float b5 = b * b; b5 = b5 * b5 * b;
    float c5 = c * c; c5 = c5 * c5 * c;
    return SIGMA_F * (c5 - 6.0f * b5 + 15.0f * a5);
}

__device__ __forceinline__ float quintic_grad_w(float d) {
    float a = fmaxf(0.0f, 1.0f - d);
    float b = fmaxf(0.0f, 2.0f - d);
    float c = fmaxf(0.0f, 3.0f - d);
    float a4 = a * a; a4 = a4 * a4;
    float b4 = b * b; b4 = b4 * b4;
    float c4 = c * c; c4 = c4 * c4;
    return SIGMA_F * (-5.0f * c4 + 30.0f * b4 - 75.0f * a4);
}

// --------------------------------------------------------------------------
__global__ void pack_zero_kernel(const float* __restrict__ r,
                                 const float* __restrict__ v, int N) {
    int i = blockIdx.x * blockDim.x + threadIdx.x;
    if (i >= N) return;
    float4 a = make_float4(__ldg(&r[3*i]), __ldg(&r[3*i+1]), __ldg(&r[3*i+2]), 0.0f);
    float4 b = make_float4(__ldg(&v[3*i]), __ldg(&v[3*i+1]), __ldg(&v[3*i+2]), 0.0f);
    g_pack[i].a = a;
    g_pack[i].b = b;
    g_counts[i] = 0;
}

// --------------------------------------------------------------------------
// slot-based counting scatter; 4 edges per thread via int4 loads
__global__ void scatter_kernel(const int* __restrict__ i_s,
                               const int* __restrict__ j_s, int E) {
    int t = blockIdx.x * blockDim.x + threadIdx.x;
    int base = t * 4;
    if (base + 3 < E) {
        int4 ii = *(const int4*)(i_s + base);
        int4 jj = *(const int4*)(j_s + base);
        int p;
        p = atomicAdd(&g_counts[ii.x], 1); if (p < SLOT) g_slots[(ii.x << SLOT_SHIFT) + p] = jj.x;
        p = atomicAdd(&g_counts[ii.y], 1); if (p < SLOT) g_slots[(ii.y << SLOT_SHIFT) + p] = jj.y;
        p = atomicAdd(&g_counts[ii.z], 1); if (p < SLOT) g_slots[(ii.z << SLOT_SHIFT) + p] = jj.z;
        p = atomicAdd(&g_counts[ii.w], 1); if (p < SLOT) g_slots[(ii.w << SLOT_SHIFT) + p] = jj.w;
    } else {
        for (int e = base; e < E; e++) {
            int i = i_s[e];
            int p = atomicAdd(&g_counts[i], 1);
            if (p < SLOT) g_slots[(i << SLOT_SHIFT) + p] = j_s[e];
        }
    }
}

// --------------------------------------------------------------------------
// 8 lanes per particle; int4 row load covers 32 slots/iter (mean degree),
// 4 predicated gathers per lane -> MLP=4 with full lane utilization at deg~32.
__global__ void rho_gather_kernel(int N) {
    int tid = blockIdx.x * blockDim.x + threadIdx.x;
    int i = tid >> 3;
    int sl = threadIdx.x & 7;
    if (i >= N) return;
    int deg = g_counts[i];
    if (deg > SLOT) deg = SLOT;
    const int4* row4 = (const int4*)&g_slots[i << SLOT_SHIFT];
    float4 Pi = g_pack[i].a;
    float sum = 0.0f;
    for (int t = 0; t * 32 < deg; t++) {
        int4 jj = row4[t * 8 + sl];           // always in-bounds (row = 128 ints)
        int s0 = t * 32 + 4 * sl;
        #pragma unroll
        for (int u = 0; u < 4; u++) {
            int j = (u == 0) ? jj.x : (u == 1) ? jj.y : (u == 2) ? jj.z : jj.w;
            if (s0 + u < deg) {
                float4 Pj = g_pack[j].a;
                float dx = Pi.x - Pj.x, dy = Pi.y - Pj.y, dz = Pi.z - Pj.z;
                sum += quintic_w(sqrtf(dx*dx + dy*dy + dz*dz));
            }
        }
    }
    #pragma unroll
    for (int o = 4; o; o >>= 1) sum += __shfl_xor_sync(~0u, sum, o);
    if (sl == 0) g_pack[i].a.w = sum;
}

// --------------------------------------------------------------------------
// 16 lanes per particle; preloaded int4 (64 slots/iter), predicated gathers;
// writes all 8 output columns via two float4 stores.
__global__ void force_gather_kernel(float* __restrict__ out, int N) {
    int tid = blockIdx.x * blockDim.x + threadIdx.x;
    int i = tid >> 4;
    int sl = threadIdx.x & 15;
    if (i >= N) return;
    int deg = g_counts[i];
    if (deg > SLOT) deg = SLOT;
    const int4* row4 = (const int4*)&g_slots[i << SLOT_SHIFT];
    float4 Pa_i = g_pack[i].a;
    float4 Pb_i = g_pack[i].b;
    float rho_i = Pa_i.w;
    float inv_i = __fdividef(1.0f, rho_i);
    float inv_i2 = inv_i * inv_i;

    float ax = 0.0f, ay = 0.0f, az = 0.0f;
    for (int t = 0; t * 64 < deg; t++) {
        int4 jj = row4[t * 16 + sl];
        int s0 = t * 64 + 4 * sl;
        #pragma unroll
        for (int u = 0; u < 4; u++) {
            int j = (u == 0) ? jj.x : (u == 1) ? jj.y : (u == 2) ? jj.z : jj.w;
            if (s0 + u < deg) {
                float4 Pa_j = g_pack[j].a;
                float4 Pb_j = g_pack[j].b;
                float dx = Pa_i.x - Pa_j.x, dy = Pa_i.y - Pa_j.y, dz = Pa_i.z - Pa_j.z;
                float d = sqrtf(dx*dx + dy*dy + dz*dz);
                float rho_j = Pa_j.w;
                // p_ij = (rho_j*p_i + rho_i*p_j)/(rho_i+rho_j) = 100*(2 rho_i rho_j/s - 1)
                float inv_s = __fdividef(1.0f, rho_i + rho_j);
                float p_ij = P_REF_F * (2.0f * rho_i * rho_j * inv_s - 1.0f);
                float inv_j = __fdividef(1.0f, rho_j);
                float wvol = inv_i2 + inv_j * inv_j;
                float c = wvol * quintic_grad_w(d) * __fdividef(1.0f, d + EPS_F);
                float dvx = Pb_i.x - Pb_j.x, dvy = Pb_i.y - Pb_j.y, dvz = Pb_i.z - Pb_j.z;
                ax += c * (-p_ij * dx + ETA_IJ_F * dvx);
                ay += c * (-p_ij * dy + ETA_IJ_F * dvy);
                az += c * (-p_ij * dz + ETA_IJ_F * dvz);
            }
        }
    }
    #pragma unroll
    for (int o = 8; o; o >>= 1) {
        ax += __shfl_xor_sync(~0u, ax, o);
        ay += __shfl_xor_sync(~0u, ay, o);
        az += __shfl_xor_sync(~0u, az, o);
    }
    if (sl == 0) {
        float4* o4 = (float4*)(out + 8 * i);
        o4[0] = make_float4(rho_i, P_REF_F * (rho_i - 1.0f), ax, ay);
        o4[1] = make_float4(az, 0.0f, 0.0f, 0.0f);
    }
}

// --------------------------------------------------------------------------
extern "C" void kernel_launch(void* const* d_in, const int* in_sizes, int n_in,
                              void* d_out, int out_size) {
    const float* r   = (const float*)d_in[0];
    const float* v   = (const float*)d_in[1];
    const int*   i_s = (const int*)d_in[2];
    const int*   j_s = (const int*)d_in[3];
    float* out = (float*)d_out;

    int N = in_sizes[0] / 3;
    int E = in_sizes[2];

    const int TB = 256;
    pack_zero_kernel<<<(N + TB - 1) / TB, TB>>>(r, v, N);
    int nthreads = (E + 3) / 4;
    scatter_kernel<<<(nthreads + TB - 1) / TB, TB>>>(i_s, j_s, E);
    // rho: 8 lanes/particle -> 32 particles per 256-thread block
    rho_gather_kernel<<<(N + 31) / 32, TB>>>(N);
    // force: 16 lanes/particle -> 16 particles per 256-thread block
    force_gather_kernel<<<(N + 15) / 16, TB>>>(out, N);
}